// round 9
// baseline (speedup 1.0000x reference)
#include <cuda_runtime.h>
#include <cuda_fp16.h>
#include <cstdint>

#define ROWS 16384      // B*S
#define CH   4096
#define NHD  8
#define IGD  128
#define TGD  384
#define FGD  512
#define ISZ  1024
#define NSEG 8
#define SEGL 512        // 4096 / NSEG

// ---------------- scratch ----------------
__device__ float g_csum[(size_t)ROWS * CH];        // scanned cumsum (fp32, LN input)
__device__ float g_part[(size_t)4 * NSEG * CH];    // segment sums

__device__ __align__(16) uint16_t csum16[(size_t)ROWS * CH];        // pre-scan GEMM out
__device__ __align__(16) uint16_t gate16[(size_t)ROWS * NHD * TGD]; // gates fp16
__device__ __align__(16) uint16_t lci16 [(size_t)ROWS * ISZ];
__device__ __align__(16) uint16_t rci16 [(size_t)ROWS * ISZ];

// ---------------- activation planes: single fp16 ----------------
__device__ __align__(16) uint16_t is_p  [(size_t)ROWS * ISZ];
__device__ __align__(16) uint16_t cell_p[(size_t)ROWS * NHD * TGD];
__device__ __align__(16) uint16_t hpre_p[(size_t)ROWS * NHD * FGD];
__device__ __align__(16) uint16_t hp_p  [(size_t)ROWS * NHD * FGD];
__device__ __align__(16) uint16_t pre_p [(size_t)ROWS * ISZ];
// ---------------- weight planes: single fp16, transposed [N][K] ----------------
__device__ __align__(16) uint16_t wcs_p[(size_t)CH * ISZ];
__device__ __align__(16) uint16_t wx_p [(size_t)ISZ * ISZ];
__device__ __align__(16) uint16_t wg_p [(size_t)NHD * TGD * TGD];
__device__ __align__(16) uint16_t wf1_p[(size_t)NHD * FGD * TGD];
__device__ __align__(16) uint16_t wf2_p[(size_t)NHD * IGD * FGD];
__device__ __align__(16) uint16_t wo_p [(size_t)ISZ * ISZ];

// ---------------- helpers ----------------
__device__ __forceinline__ uint32_t smem_u32(const void* p) {
    uint32_t a;
    asm("{ .reg .u64 t; cvta.to.shared.u64 t, %1; cvt.u32.u64 %0, t; }" : "=r"(a) : "l"(p));
    return a;
}
#define CP16(dst, src) asm volatile("cp.async.cg.shared.global [%0], [%1], 16;" :: "r"(dst), "l"(src))
#define CP_COMMIT()    asm volatile("cp.async.commit_group;" ::: "memory")

__device__ __forceinline__ void ldm4(uint32_t& r0, uint32_t& r1, uint32_t& r2, uint32_t& r3, uint32_t a) {
    asm volatile("ldmatrix.sync.aligned.m8n8.x4.shared.b16 {%0,%1,%2,%3}, [%4];"
                 : "=r"(r0), "=r"(r1), "=r"(r2), "=r"(r3) : "r"(a));
}
__device__ __forceinline__ void mma16816(float* d, const uint32_t* a, const uint32_t* b) {
    asm volatile("mma.sync.aligned.m16n8k16.row.col.f32.f16.f16.f32 "
                 "{%0,%1,%2,%3},{%4,%5,%6,%7},{%8,%9},{%0,%1,%2,%3};"
                 : "+f"(d[0]), "+f"(d[1]), "+f"(d[2]), "+f"(d[3])
                 : "r"(a[0]), "r"(a[1]), "r"(a[2]), "r"(a[3]), "r"(b[0]), "r"(b[1]));
}
__device__ __forceinline__ uint32_t pack2h(float x, float y) {
    __half2 v = __floats2half2_rn(x, y);
    return *(uint32_t*)&v;
}
__device__ __forceinline__ uint2 pack4h(float4 v) {
    uint2 r;
    r.x = pack2h(v.x, v.y);
    r.y = pack2h(v.z, v.w);
    return r;
}
__device__ __forceinline__ float2 unp2(uint32_t u) { return __half22float2(*(__half2*)&u); }

// ---------------- fp16 tensor-core GEMM, double-buffered ----------------
// FLAGS: 1 mask, 2 residual(fp32 out), 4 fp16-out remap (out_x), 8 fused-combine (ffn2), 16 fp16-out plain
#define P_A  0
#define P_B  8192
#define STG  16384
#define SMT  32768

template <int FLAGS>
__global__ void __launch_bounds__(256, 2) hgemm_k(
    const uint16_t* __restrict__ Ap, int lda, int aoff,
    const uint16_t* __restrict__ Bp, long boff,
    const float* __restrict__ bias, int biasoff,
    float* __restrict__ C, int ldc, int coff,
    uint16_t* __restrict__ Cp,
    int N, int K,
    const unsigned char* __restrict__ mask,
    const float* __restrict__ resid,
    const uint16_t* __restrict__ g16,   // gates (FLAG8)
    const uint16_t* __restrict__ l16, const uint16_t* __restrict__ r16)
{
    extern __shared__ char smem[];
    const uint32_t sb = smem_u32(smem);
    const int tid = threadIdx.x, wid = tid >> 5, lane = tid & 31;

    Ap += (long)blockIdx.z * aoff;
    Bp += (long)blockIdx.z * boff;
    bias += (long)blockIdx.z * biasoff;
    C  += (long)blockIdx.z * coff;
    Cp += (FLAGS & 16) ? (long)blockIdx.z * coff : 0;

    const int m0 = blockIdx.y * 128;
    const int n0 = blockIdx.x * 128;
    const int warpM = (wid & 1) * 64;
    const int warpN = (wid >> 1) * 32;

    const int rowA = warpM + (lane & 15);
    const int hiA  = (lane >> 4) & 1;
    const int swA  = (rowA >> 1) & 3;
    const uint32_t aRow = sb + P_A + (uint32_t)rowA * 64;

    const int rowB = warpN + (lane & 7) + ((lane & 16) >> 1);
    const int hiB  = (lane >> 3) & 1;
    const int swB  = (rowB >> 1) & 3;
    const uint32_t bRow = sb + P_B + (uint32_t)rowB * 64;

    const int su0 = tid, su1 = tid + 256;
    const int sr0 = su0 >> 2, sc0 = su0 & 3;
    const int sr1 = su1 >> 2, sc1 = su1 & 3;
    const uint32_t sd0 = (uint32_t)sr0 * 64 + ((uint32_t)(sc0 ^ ((sr0 >> 1) & 3)) << 4);
    const uint32_t sd1 = (uint32_t)sr1 * 64 + ((uint32_t)(sc1 ^ ((sr1 >> 1) & 3)) << 4);

    float acc[4][4][4];
#pragma unroll
    for (int i = 0; i < 4; i++)
#pragma unroll
        for (int j = 0; j < 4; j++)
#pragma unroll
            for (int q = 0; q < 4; q++) acc[i][j][q] = 0.f;

    const int nch = K >> 5;

#define STAGE(c, bs) do { \
        const int _k0 = (c) << 5; \
        const uint32_t _b = sb + (bs) * STG; \
        size_t _sa = (size_t)(m0 + sr0) * lda + _k0 + sc0 * 8; \
        CP16(_b + P_A + sd0, Ap + _sa); \
        size_t _sb2 = (size_t)(n0 + sr0) * K + _k0 + sc0 * 8; \
        CP16(_b + P_B + sd0, Bp + _sb2); \
        _sa = (size_t)(m0 + sr1) * lda + _k0 + sc1 * 8; \
        CP16(_b + P_A + sd1, Ap + _sa); \
        _sb2 = (size_t)(n0 + sr1) * K + _k0 + sc1 * 8; \
        CP16(_b + P_B + sd1, Bp + _sb2); \
        CP_COMMIT(); \
    } while (0)

    STAGE(0, 0);
    for (int c = 0; c < nch; c++) {
        const int bs = c & 1;
        if (c + 1 < nch) {
            STAGE(c + 1, bs ^ 1);
            asm volatile("cp.async.wait_group 1;" ::: "memory");
        } else {
            asm volatile("cp.async.wait_group 0;" ::: "memory");
        }
        __syncthreads();

        const uint32_t bb = (uint32_t)bs * STG;
#pragma unroll
        for (int ks = 0; ks < 2; ks++) {
            const uint32_t ca = ((uint32_t)((2 * ks + hiA) ^ swA)) << 4;
            const uint32_t cb = ((uint32_t)((2 * ks + hiB) ^ swB)) << 4;
            uint32_t bf[4][2];
            ldm4(bf[0][0], bf[0][1], bf[1][0], bf[1][1], bRow + bb + cb);
            ldm4(bf[2][0], bf[2][1], bf[3][0], bf[3][1], bRow + bb + 1024 + cb);
#pragma unroll
            for (int mf = 0; mf < 4; mf++) {
                uint32_t af[4];
                ldm4(af[0], af[1], af[2], af[3], aRow + bb + mf * 1024 + ca);
#pragma unroll
                for (int nf = 0; nf < 4; nf++)
                    mma16816(acc[mf][nf], af, bf[nf]);
            }
        }
        __syncthreads();
    }
#undef STAGE

    // ---------------- epilogue ----------------
#pragma unroll
    for (int mf = 0; mf < 4; mf++) {
        long rA = m0 + warpM + mf * 16 + (lane >> 2);
        long rB = rA + 8;
        float zfA = 1.f, zfB = 1.f;
        if (FLAGS & 1) { zfA = mask[rA] ? 0.f : 1.f; zfB = mask[rB] ? 0.f : 1.f; }
#pragma unroll
        for (int nf = 0; nf < 4; nf++) {
            int gn = n0 + warpN + nf * 8 + (lane & 3) * 2;
            float b0 = bias[gn], b1 = bias[gn + 1];
            float x0 = acc[mf][nf][0] + b0, x1 = acc[mf][nf][1] + b1;
            float y0 = acc[mf][nf][2] + b0, y1 = acc[mf][nf][3] + b1;
            if (FLAGS & 1) { x0 *= zfA; x1 *= zfA; y0 *= zfB; y1 *= zfB; }
            if (FLAGS & 2) {
                x0 += resid[rA * N + gn]; x1 += resid[rA * N + gn + 1];
                y0 += resid[rB * N + gn]; y1 += resid[rB * N + gn + 1];
            }
            if (FLAGS & 4) {
                int cn = (gn >> 7) * TGD + IGD + (gn & 127);
                *(uint32_t*)&Cp[rA * ldc + cn] = pack2h(x0, x1);
                *(uint32_t*)&Cp[rB * ldc + cn] = pack2h(y0, y1);
            } else if (FLAGS & 8) {
                int gc = blockIdx.z * IGD + gn;
                const uint16_t* gbA = g16 + rA * (NHD * TGD) + blockIdx.z * TGD;
                const uint16_t* gbB = g16 + rB * (NHD * TGD) + blockIdx.z * TGD;
                float2 lgA = unp2(*(const uint32_t*)&gbA[gn]);
                float2 igA = unp2(*(const uint32_t*)&gbA[IGD + gn]);
                float2 rgA = unp2(*(const uint32_t*)&gbA[2 * IGD + gn]);
                float2 lgB = unp2(*(const uint32_t*)&gbB[gn]);
                float2 igB = unp2(*(const uint32_t*)&gbB[IGD + gn]);
                float2 rgB = unp2(*(const uint32_t*)&gbB[2 * IGD + gn]);
                float2 liA = unp2(*(const uint32_t*)&l16[rA * ISZ + gc]);
                float2 riA = unp2(*(const uint32_t*)&r16[rA * ISZ + gc]);
                float2 liB = unp2(*(const uint32_t*)&l16[rB * ISZ + gc]);
                float2 riB = unp2(*(const uint32_t*)&r16[rB * ISZ + gc]);
                float o0 = liA.x * lgA.x + igA.x * x0 + riA.x * rgA.x;
                float o1 = liA.y * lgA.y + igA.y * x1 + riA.y * rgA.y;
                float o2 = liB.x * lgB.x + igB.x * y0 + riB.x * rgB.x;
                float o3 = liB.y * lgB.y + igB.y * y1 + riB.y * rgB.y;
                *(uint32_t*)&Cp[rA * ISZ + gc] = pack2h(o0, o1);
                *(uint32_t*)&Cp[rB * ISZ + gc] = pack2h(o2, o3);
            } else if (FLAGS & 16) {
                *(uint32_t*)&Cp[rA * ldc + gn] = pack2h(x0, x1);
                *(uint32_t*)&Cp[rB * ldc + gn] = pack2h(y0, y1);
            } else {
                *(float2*)(C + rA * ldc + gn) = make_float2(x0, x1);
                *(float2*)(C + rB * ldc + gn) = make_float2(y0, y1);
            }
        }
    }
}

// ---------------- conversion kernels ----------------
__global__ void __launch_bounds__(256) icvt_k(const float* __restrict__ src,
                                              uint16_t* __restrict__ p) {
    size_t i = (size_t)blockIdx.x * 256 + threadIdx.x;
    float4 v = ((const float4*)src)[i];
    ((uint2*)p)[i] = pack4h(v);
}

// W [K][N] fp32 -> single fp16 plane [N][K]
__global__ void __launch_bounds__(256) wsplit_k(const float* __restrict__ W,
                                                uint16_t* __restrict__ Tp,
                                                int K, int N) {
    __shared__ float tile[32][33];
    const int n0 = blockIdx.x * 32, k0 = blockIdx.y * 32;
    const float* Wp = W + (size_t)blockIdx.z * K * N;
    uint16_t* Hp = Tp + (size_t)blockIdx.z * K * N;
    int tx = threadIdx.x & 31, ty = threadIdx.x >> 5;
#pragma unroll
    for (int i = 0; i < 4; i++)
        tile[ty + 8 * i][tx] = Wp[(size_t)(k0 + ty + 8 * i) * N + n0 + tx];
    __syncthreads();
#pragma unroll
    for (int i = 0; i < 4; i++) {
        __half h = __float2half_rn(tile[tx][ty + 8 * i]);
        Hp[(size_t)(n0 + ty + 8 * i) * K + k0 + tx] = *(uint16_t*)&h;
    }
}

// ---------------- block reduce ----------------
__device__ __forceinline__ void block_reduce2(float& a, float& b) {
    __shared__ float sh[64];
    int lane = threadIdx.x & 31, wid = threadIdx.x >> 5;
#pragma unroll
    for (int o = 16; o > 0; o >>= 1) {
        a += __shfl_xor_sync(0xffffffffu, a, o);
        b += __shfl_xor_sync(0xffffffffu, b, o);
    }
    if (lane == 0) { sh[wid] = a; sh[32 + wid] = b; }
    __syncthreads();
    if (threadIdx.x < 32) {
        a = (lane < 8) ? sh[lane] : 0.f;
        b = (lane < 8) ? sh[32 + lane] : 0.f;
#pragma unroll
        for (int o = 4; o > 0; o >>= 1) {
            a += __shfl_xor_sync(0xffffffffu, a, o);
            b += __shfl_xor_sync(0xffffffffu, b, o);
        }
        if (lane == 0) { sh[0] = a; sh[32] = b; }
    }
    __syncthreads();
    a = sh[0]; b = sh[32];
}

// ---------------- segmented cumsum (fp16 in, fp32 out) ----------------
__global__ void __launch_bounds__(256) cumsumA_k() {
    int idx = blockIdx.x * 256 + threadIdx.x;     // (b*NSEG+seg)*4096 + c
    int c = idx & 4095;
    int t = idx >> 12;
    int b = t >> 3, seg = t & 7;
    const uint16_t* p = csum16 + ((size_t)b << 24) + (size_t)(seg * SEGL) * CH + c;
    float s = 0.f;
#pragma unroll 8
    for (int i = 0; i < SEGL; i++) s += __half2float(*(const __half*)&p[(size_t)i * CH]);
    g_part[idx] = s;
}

__global__ void __launch_bounds__(256) cumsumC_k() {
    int idx = blockIdx.x * 256 + threadIdx.x;
    int c = idx & 4095;
    int t = idx >> 12;
    int b = t >> 3, seg = t & 7;
    const uint16_t* p = csum16 + ((size_t)b << 24) + (size_t)(seg * SEGL) * CH + c;
    float* q = g_csum + ((size_t)b << 24) + (size_t)(seg * SEGL) * CH + c;
    float acc = 0.f;
    if (c < 2048) {
#pragma unroll
        for (int s2 = 0; s2 < NSEG; s2++)
            if (s2 < seg) acc += g_part[((b * NSEG + s2) << 12) + c];
#pragma unroll 8
        for (int i = 0; i < SEGL; i++) {
            acc += __half2float(*(const __half*)&p[(size_t)i * CH]);
            q[(size_t)i * CH] = acc;
        }
    } else {
#pragma unroll
        for (int s2 = 0; s2 < NSEG; s2++)
            if (s2 > seg) acc += g_part[((b * NSEG + s2) << 12) + c];
#pragma unroll 8
        for (int i = SEGL - 1; i >= 0; i--) {
            acc += __half2float(*(const __half*)&p[(size_t)i * CH]);
            q[(size_t)i * CH] = acc;
        }
    }
}

// ---------------- LN lc/rc -> cell plane + relu'd lci/rci (fp16) ----------------
__global__ void __launch_bounds__(256) ln_lcrc_k(
    const float* __restrict__ gl, const float* __restrict__ bl,
    const float* __restrict__ gr, const float* __restrict__ br_)
{
    const int row = blockIdx.x, side = blockIdx.y;
    const float4* x4 = (const float4*)(g_csum + (size_t)row * CH + side * 2048);
    float4 v[2];
    float s = 0.f, ss = 0.f;
#pragma unroll
    for (int k = 0; k < 2; k++) {
        v[k] = x4[threadIdx.x + k * 256];
        s  += v[k].x + v[k].y + v[k].z + v[k].w;
        ss += v[k].x * v[k].x + v[k].y * v[k].y + v[k].z * v[k].z + v[k].w * v[k].w;
    }
    block_reduce2(s, ss);
    float m  = s * (1.f / 2048.f);
    float rs = rsqrtf(ss * (1.f / 2048.f) - m * m + 1e-6f);

    const float4* g4 = (const float4*)(side ? gr  : gl);
    const float4* b4 = (const float4*)(side ? br_ : bl);
    uint16_t* ibuf = side ? rci16 : lci16;
#pragma unroll
    for (int k = 0; k < 2; k++) {
        int c4 = threadIdx.x + k * 256;
        int c  = c4 * 4;
        float4 gv = g4[c4], bv = b4[c4], xv = v[k];
        float4 o;
        o.x = (xv.x - m) * rs * gv.x + bv.x;
        o.y = (xv.y - m) * rs * gv.y + bv.y;
        o.z = (xv.z - m) * rs * gv.z + bv.z;
        o.w = (xv.w - m) * rs * gv.w + bv.w;
        if (c < 1024) {
            int h = c >> 7, ig = c & 127;
            size_t o16 = (size_t)row * (NHD * TGD) + h * TGD + side * 256 + ig;
            *(uint2*)&cell_p[o16] = pack4h(o);
        } else {
            o.x = fmaxf(o.x, 0.f); o.y = fmaxf(o.y, 0.f);
            o.z = fmaxf(o.z, 0.f); o.w = fmaxf(o.w, 0.f);
            *(uint2*)&ibuf[(size_t)row * ISZ + (c - 1024)] = pack4h(o);
        }
    }
}

// ---------------- LN gates + sigmoid (fp16 in place) ----------------
__global__ void __launch_bounds__(256) ln_g_k(const float* __restrict__ gg,
                                              const float* __restrict__ bg) {
    const int row = blockIdx.x;
    uint2* x2 = (uint2*)(gate16 + (size_t)row * (NHD * TGD));
    float4 v[3];
    float s = 0.f, ss = 0.f;
#pragma unroll
    for (int k = 0; k < 3; k++) {
        uint2 u = x2[threadIdx.x + k * 256];
        float2 a = unp2(u.x), b = unp2(u.y);
        v[k] = make_float4(a.x, a.y, b.x, b.y);
        s  += v[k].x + v[k].y + v[k].z + v[k].w;
        ss += v[k].x * v[k].x + v[k].y * v[k].y + v[k].z * v[k].z + v[k].w * v[k].w;
    }
    block_reduce2(s, ss);
    float m  = s * (1.f / 3072.f);
    float rs = rsqrtf(ss * (1.f / 3072.f) - m * m + 1e-6f);
    const float4* g4 = (const float4*)gg;
    const float4* b4 = (const float4*)bg;
#pragma unroll
    for (int k = 0; k < 3; k++) {
        int c4 = threadIdx.x + k * 256;
        float4 gv = g4[c4], bv = b4[c4], xv = v[k];
        float4 o;
        o.x = 1.f / (1.f + __expf(-((xv.x - m) * rs * gv.x + bv.x)));
        o.y = 1.f / (1.f + __expf(-((xv.y - m) * rs * gv.y + bv.y)));
        o.z = 1.f / (1.f + __expf(-((xv.z - m) * rs * gv.z + bv.z)));
        o.w = 1.f / (1.f + __expf(-((xv.w - m) * rs * gv.w + bv.w)));
        uint2 w;
        w.x = pack2h(o.x, o.y);
        w.y = pack2h(o.z, o.w);
        x2[c4] = w;
    }
}

// ---------------- LN ffn hidden (fp16 in) + relu -> hp plane ----------------
__global__ void __launch_bounds__(256) ln_f_k(const float* __restrict__ gf,
                                              const float* __restrict__ bf) {
    const int row = blockIdx.x;
    const uint2* x2 = (const uint2*)(hpre_p + (size_t)row * (NHD * FGD));
    float4 v[4];
    float s = 0.f, ss = 0.f;
#pragma unroll
    for (int k = 0; k < 4; k++) {
        uint2 u = x2[threadIdx.x + k * 256];
        float2 a = unp2(u.x), b = unp2(u.y);
        v[k] = make_float4(a.x, a.y, b.x, b.y);
        s  += v[k].x + v[k].y + v[k].z + v[k].w;
        ss += v[k].x * v[k].x + v[k].y * v[k].y + v[k].z * v[k].z + v[k].w * v[k].w;
    }
    block_reduce2(s, ss);
    float m  = s * (1.f / 4096.f);
    float rs = rsqrtf(ss * (1.f / 4096.f) - m * m + 1e-6f);
    const float4* g4 = (const float4*)gf;
    const float4* b4 = (const float4*)bf;
#pragma unroll
    for (int k = 0; k < 4; k++) {
        int c4 = threadIdx.x + k * 256;
        float4 gv = g4[c4], bv = b4[c4], xv = v[k];
        float4 o;
        o.x = fmaxf((xv.x - m) * rs * gv.x + bv.x, 0.f);
        o.y = fmaxf((xv.y - m) * rs * gv.y + bv.y, 0.f);
        o.z = fmaxf((xv.z - m) * rs * gv.z + bv.z, 0.f);
        o.w = fmaxf((xv.w - m) * rs * gv.w + bv.w, 0.f);
        *(uint2*)&hp_p[(size_t)row * (NHD * FGD) + c4 * 4] = pack4h(o);
    }
}

// ---------------- host ----------------
extern "C" void kernel_launch(void* const* d_in, const int* in_sizes, int n_in,
                              void* d_out, int out_size) {
    const float* inputs = (const float*)d_in[0];
    const unsigned char* mask = (const unsigned char*)d_in[1];
    const float* W_csum = (const float*)d_in[2];
    const float* b_csum = (const float*)d_in[3];
    const float* W_x    = (const float*)d_in[4];
    const float* b_x    = (const float*)d_in[5];
    const float* gl     = (const float*)d_in[6];
    const float* bel    = (const float*)d_in[7];
    const float* gr     = (const float*)d_in[8];
    const float* ber    = (const float*)d_in[9];
    const float* ggain  = (const float*)d_in[10];
    const float* beg    = (const float*)d_in[11];
    const float* gf     = (const float*)d_in[12];
    const float* bef    = (const float*)d_in[13];
    const float* W_g    = (const float*)d_in[14];
    const float* b_g    = (const float*)d_in[15];
    const float* W_f1   = (const float*)d_in[16];
    const float* b_f1   = (const float*)d_in[17];
    const float* W_f2   = (const float*)d_in[18];
    const float* b_f2   = (const float*)d_in[19];
    const float* W_o    = (const float*)d_in[20];
    const float* b_o    = (const float*)d_in[21];
    float* out = (float*)d_out;

    uint16_t *pcs16, *pg16, *pl16, *pr16;
    cudaGetSymbolAddress((void**)&pcs16, csum16);
    cudaGetSymbolAddress((void**)&pg16,  gate16);
    cudaGetSymbolAddress((void**)&pl16,  lci16);
    cudaGetSymbolAddress((void**)&pr16,  rci16);
    uint16_t *pis, *pcell, *phpre, *php, *ppre;
    uint16_t *pwcs, *pwx, *pwg, *pwf1, *pwf2, *pwo;
    cudaGetSymbolAddress((void**)&pis,   is_p);
    cudaGetSymbolAddress((void**)&pcell, cell_p);
    cudaGetSymbolAddress((void**)&phpre, hpre_p);
    cudaGetSymbolAddress((void**)&php,   hp_p);
    cudaGetSymbolAddress((void**)&ppre,  pre_p);
    cudaGetSymbolAddress((void**)&pwcs, wcs_p);
    cudaGetSymbolAddress((void**)&pwx,  wx_p);
    cudaGetSymbolAddress((void**)&pwg,  wg_p);
    cudaGetSymbolAddress((void**)&pwf1, wf1_p);
    cudaGetSymbolAddress((void**)&pwf2, wf2_p);
    cudaGetSymbolAddress((void**)&pwo,  wo_p);

    cudaFuncSetAttribute(hgemm_k<2>,  cudaFuncAttributeMaxDynamicSharedMemorySize, SMT);
    cudaFuncSetAttribute(hgemm_k<4>,  cudaFuncAttributeMaxDynamicSharedMemorySize, SMT);
    cudaFuncSetAttribute(hgemm_k<8>,  cudaFuncAttributeMaxDynamicSharedMemorySize, SMT);
    cudaFuncSetAttribute(hgemm_k<16>, cudaFuncAttributeMaxDynamicSharedMemorySize, SMT);
    cudaFuncSetAttribute(hgemm_k<17>, cudaFuncAttributeMaxDynamicSharedMemorySize, SMT);

    dim3 blk(256);

    // ---- conversions ----
    icvt_k<<<ROWS * ISZ / 1024, blk>>>(inputs, pis);
    wsplit_k<<<dim3(CH / 32, ISZ / 32, 1), blk>>>(W_csum, pwcs, ISZ, CH);
    wsplit_k<<<dim3(ISZ / 32, ISZ / 32, 1), blk>>>(W_x, pwx, ISZ, ISZ);
    wsplit_k<<<dim3(TGD / 32, TGD / 32, NHD), blk>>>(W_g, pwg, TGD, TGD);
    wsplit_k<<<dim3(FGD / 32, TGD / 32, NHD), blk>>>(W_f1, pwf1, TGD, FGD);
    wsplit_k<<<dim3(IGD / 32, FGD / 32, NHD), blk>>>(W_f2, pwf2, FGD, IGD);
    wsplit_k<<<dim3(ISZ / 32, ISZ / 32, 1), blk>>>(W_o, pwo, ISZ, ISZ);

    // 1) csum GEMM (masked, fp16 out)
    hgemm_k<17><<<dim3(CH / 128, ROWS / 128, 1), blk, SMT>>>(
        pis, ISZ, 0, pwcs, 0, b_csum, 0,
        nullptr, CH, 0, pcs16, CH, ISZ, mask, nullptr, nullptr, nullptr, nullptr);
    // 2) out_x GEMM -> cell plane (remap)
    hgemm_k<4><<<dim3(ISZ / 128, ROWS / 128, 1), blk, SMT>>>(
        pis, ISZ, 0, pwx, 0, b_x, 0,
        nullptr, NHD * TGD, 0, pcell, ISZ, ISZ, nullptr, nullptr, nullptr, nullptr, nullptr);
    // 3) segmented cumsum (fp16 in -> fp32 out)
    cumsumA_k<<<512, 256>>>();
    cumsumC_k<<<512, 256>>>();
    // 4) LN lc/rc
    ln_lcrc_k<<<dim3(ROWS, 2), 256>>>(gl, bel, gr, ber);
    // 5) gates GEMM (fp16 out)
    hgemm_k<16><<<dim3(TGD / 128, ROWS / 128, NHD), blk, SMT>>>(
        pcell, NHD * TGD, TGD, pwg, (long)TGD * TGD, b_g, TGD,
        nullptr, NHD * TGD, TGD, pg16, TGD, TGD, nullptr, nullptr, nullptr, nullptr, nullptr);
    // 6) LN gates + sigmoid (fp16 in place)
    ln_g_k<<<ROWS, 256>>>(ggain, beg);
    // 7) ffn1 GEMM -> fp16 pre-LN hidden
    hgemm_k<16><<<dim3(FGD / 128, ROWS / 128, NHD), blk, SMT>>>(
        pcell, NHD * TGD, TGD, pwf1, (long)FGD * TGD, b_f1, FGD,
        nullptr, NHD * FGD, FGD, phpre, FGD, TGD, nullptr, nullptr, nullptr, nullptr, nullptr);
    // 8) LN ffn + relu -> hp plane
    ln_f_k<<<ROWS, 256>>>(gf, bef);
    // 9) ffn2 GEMM + fused combine -> pre plane
    hgemm_k<8><<<dim3(IGD / 128, ROWS / 128, NHD), blk, SMT>>>(
        php, NHD * FGD, FGD, pwf2, (long)IGD * FGD, b_f2, IGD,
        nullptr, ISZ, IGD, ppre, IGD, FGD, nullptr, nullptr, pg16, pl16, pr16);
    // 10) final GEMM + residual
    hgemm_k<2><<<dim3(ISZ / 128, ROWS / 128, 1), blk, SMT>>>(
        ppre, ISZ, 0, pwo, 0, b_o, 0,
        out, ISZ, 0, nullptr, ISZ, ISZ, nullptr, inputs, nullptr, nullptr, nullptr);
}

// round 10
// speedup vs baseline: 1.0019x; 1.0019x over previous
#include <cuda_runtime.h>
#include <cuda_fp16.h>
#include <cstdint>

#define ROWS 16384      // B*S
#define CH   4096
#define NHD  8
#define IGD  128
#define TGD  384
#define FGD  512
#define ISZ  1024
#define NSEG 8
#define SEGL 512        // 4096 / NSEG

// ---------------- scratch ----------------
__device__ float g_csum[(size_t)ROWS * CH];        // scanned cumsum (fp32, LN input)
__device__ float g_part[(size_t)4 * NSEG * CH];    // segment sums

__device__ __align__(16) uint16_t csum16[(size_t)ROWS * CH];        // pre-scan GEMM out
__device__ __align__(16) uint16_t gate16[(size_t)ROWS * NHD * TGD]; // gates fp16
__device__ __align__(16) uint16_t lci16 [(size_t)ROWS * ISZ];
__device__ __align__(16) uint16_t rci16 [(size_t)ROWS * ISZ];

// ---------------- activation planes: single fp16 ----------------
__device__ __align__(16) uint16_t is_p  [(size_t)ROWS * ISZ];
__device__ __align__(16) uint16_t cell_p[(size_t)ROWS * NHD * TGD];
__device__ __align__(16) uint16_t hpre_p[(size_t)ROWS * NHD * FGD];
__device__ __align__(16) uint16_t hp_p  [(size_t)ROWS * NHD * FGD];
__device__ __align__(16) uint16_t pre_p [(size_t)ROWS * ISZ];
// ---------------- weight planes: single fp16, transposed [N][K] ----------------
__device__ __align__(16) uint16_t wcs_p[(size_t)CH * ISZ];
__device__ __align__(16) uint16_t wx_p [(size_t)ISZ * ISZ];
__device__ __align__(16) uint16_t wg_p [(size_t)NHD * TGD * TGD];
__device__ __align__(16) uint16_t wf1_p[(size_t)NHD * FGD * TGD];
__device__ __align__(16) uint16_t wf2_p[(size_t)NHD * IGD * FGD];
__device__ __align__(16) uint16_t wo_p [(size_t)ISZ * ISZ];

// ---------------- helpers ----------------
__device__ __forceinline__ uint32_t smem_u32(const void* p) {
    uint32_t a;
    asm("{ .reg .u64 t; cvta.to.shared.u64 t, %1; cvt.u32.u64 %0, t; }" : "=r"(a) : "l"(p));
    return a;
}
#define CP16(dst, src) asm volatile("cp.async.cg.shared.global [%0], [%1], 16;" :: "r"(dst), "l"(src))
#define CP_COMMIT()    asm volatile("cp.async.commit_group;" ::: "memory")

__device__ __forceinline__ void ldm4(uint32_t& r0, uint32_t& r1, uint32_t& r2, uint32_t& r3, uint32_t a) {
    asm volatile("ldmatrix.sync.aligned.m8n8.x4.shared.b16 {%0,%1,%2,%3}, [%4];"
                 : "=r"(r0), "=r"(r1), "=r"(r2), "=r"(r3) : "r"(a));
}
__device__ __forceinline__ void mma16816(float* d, const uint32_t* a, const uint32_t* b) {
    asm volatile("mma.sync.aligned.m16n8k16.row.col.f32.f16.f16.f32 "
                 "{%0,%1,%2,%3},{%4,%5,%6,%7},{%8,%9},{%0,%1,%2,%3};"
                 : "+f"(d[0]), "+f"(d[1]), "+f"(d[2]), "+f"(d[3])
                 : "r"(a[0]), "r"(a[1]), "r"(a[2]), "r"(a[3]), "r"(b[0]), "r"(b[1]));
}
__device__ __forceinline__ uint32_t pack2h(float x, float y) {
    __half2 v = __floats2half2_rn(x, y);
    return *(uint32_t*)&v;
}
__device__ __forceinline__ uint2 pack4h(float4 v) {
    uint2 r;
    r.x = pack2h(v.x, v.y);
    r.y = pack2h(v.z, v.w);
    return r;
}
__device__ __forceinline__ float2 unp2(uint32_t u) { return __half22float2(*(__half2*)&u); }

// ---------------- fp16 tensor-core GEMM, double-buffered ----------------
// FLAGS: 1 mask, 2 residual(fp32 out), 4 fp16-out remap (out_x), 8 fused-combine (ffn2), 16 fp16-out plain
#define P_A  0
#define P_B  8192
#define STG  16384
#define SMT  32768

template <int FLAGS>
__global__ void __launch_bounds__(256, 2) hgemm_k(
    const uint16_t* __restrict__ Ap, int lda, int aoff,
    const uint16_t* __restrict__ Bp, long boff,
    const float* __restrict__ bias, int biasoff,
    float* __restrict__ C, int ldc, int coff,
    uint16_t* __restrict__ Cp,
    int N, int K,
    const unsigned char* __restrict__ mask,
    const float* __restrict__ resid,
    const uint16_t* __restrict__ g16,   // gates (FLAG8)
    const uint16_t* __restrict__ l16, const uint16_t* __restrict__ r16)
{
    extern __shared__ char smem[];
    const uint32_t sb = smem_u32(smem);
    const int tid = threadIdx.x, wid = tid >> 5, lane = tid & 31;

    Ap += (long)blockIdx.z * aoff;
    Bp += (long)blockIdx.z * boff;
    bias += (long)blockIdx.z * biasoff;
    C  += (long)blockIdx.z * coff;
    Cp += (FLAGS & 16) ? (long)blockIdx.z * coff : 0;

    const int m0 = blockIdx.y * 128;
    const int n0 = blockIdx.x * 128;
    const int warpM = (wid & 1) * 64;
    const int warpN = (wid >> 1) * 32;

    const int rowA = warpM + (lane & 15);
    const int hiA  = (lane >> 4) & 1;
    const int swA  = (rowA >> 1) & 3;
    const uint32_t aRow = sb + P_A + (uint32_t)rowA * 64;

    const int rowB = warpN + (lane & 7) + ((lane & 16) >> 1);
    const int hiB  = (lane >> 3) & 1;
    const int swB  = (rowB >> 1) & 3;
    const uint32_t bRow = sb + P_B + (uint32_t)rowB * 64;

    const int su0 = tid, su1 = tid + 256;
    const int sr0 = su0 >> 2, sc0 = su0 & 3;
    const int sr1 = su1 >> 2, sc1 = su1 & 3;
    const uint32_t sd0 = (uint32_t)sr0 * 64 + ((uint32_t)(sc0 ^ ((sr0 >> 1) & 3)) << 4);
    const uint32_t sd1 = (uint32_t)sr1 * 64 + ((uint32_t)(sc1 ^ ((sr1 >> 1) & 3)) << 4);

    float acc[4][4][4];
#pragma unroll
    for (int i = 0; i < 4; i++)
#pragma unroll
        for (int j = 0; j < 4; j++)
#pragma unroll
            for (int q = 0; q < 4; q++) acc[i][j][q] = 0.f;

    const int nch = K >> 5;

#define STAGE(c, bs) do { \
        const int _k0 = (c) << 5; \
        const uint32_t _b = sb + (bs) * STG; \
        size_t _sa = (size_t)(m0 + sr0) * lda + _k0 + sc0 * 8; \
        CP16(_b + P_A + sd0, Ap + _sa); \
        size_t _sb2 = (size_t)(n0 + sr0) * K + _k0 + sc0 * 8; \
        CP16(_b + P_B + sd0, Bp + _sb2); \
        _sa = (size_t)(m0 + sr1) * lda + _k0 + sc1 * 8; \
        CP16(_b + P_A + sd1, Ap + _sa); \
        _sb2 = (size_t)(n0 + sr1) * K + _k0 + sc1 * 8; \
        CP16(_b + P_B + sd1, Bp + _sb2); \
        CP_COMMIT(); \
    } while (0)

    STAGE(0, 0);
    for (int c = 0; c < nch; c++) {
        const int bs = c & 1;
        if (c + 1 < nch) {
            STAGE(c + 1, bs ^ 1);
            asm volatile("cp.async.wait_group 1;" ::: "memory");
        } else {
            asm volatile("cp.async.wait_group 0;" ::: "memory");
        }
        __syncthreads();

        const uint32_t bb = (uint32_t)bs * STG;
#pragma unroll
        for (int ks = 0; ks < 2; ks++) {
            const uint32_t ca = ((uint32_t)((2 * ks + hiA) ^ swA)) << 4;
            const uint32_t cb = ((uint32_t)((2 * ks + hiB) ^ swB)) << 4;
            uint32_t bf[4][2];
            ldm4(bf[0][0], bf[0][1], bf[1][0], bf[1][1], bRow + bb + cb);
            ldm4(bf[2][0], bf[2][1], bf[3][0], bf[3][1], bRow + bb + 1024 + cb);
#pragma unroll
            for (int mf = 0; mf < 4; mf++) {
                uint32_t af[4];
                ldm4(af[0], af[1], af[2], af[3], aRow + bb + mf * 1024 + ca);
#pragma unroll
                for (int nf = 0; nf < 4; nf++)
                    mma16816(acc[mf][nf], af, bf[nf]);
            }
        }
        __syncthreads();
    }
#undef STAGE

    // ---------------- epilogue ----------------
#pragma unroll
    for (int mf = 0; mf < 4; mf++) {
        long rA = m0 + warpM + mf * 16 + (lane >> 2);
        long rB = rA + 8;
        float zfA = 1.f, zfB = 1.f;
        if (FLAGS & 1) { zfA = mask[rA] ? 0.f : 1.f; zfB = mask[rB] ? 0.f : 1.f; }
#pragma unroll
        for (int nf = 0; nf < 4; nf++) {
            int gn = n0 + warpN + nf * 8 + (lane & 3) * 2;
            float b0 = bias[gn], b1 = bias[gn + 1];
            float x0 = acc[mf][nf][0] + b0, x1 = acc[mf][nf][1] + b1;
            float y0 = acc[mf][nf][2] + b0, y1 = acc[mf][nf][3] + b1;
            if (FLAGS & 1) { x0 *= zfA; x1 *= zfA; y0 *= zfB; y1 *= zfB; }
            if (FLAGS & 2) {
                x0 += resid[rA * N + gn]; x1 += resid[rA * N + gn + 1];
                y0 += resid[rB * N + gn]; y1 += resid[rB * N + gn + 1];
            }
            if (FLAGS & 4) {
                int cn = (gn >> 7) * TGD + IGD + (gn & 127);
                *(uint32_t*)&Cp[rA * ldc + cn] = pack2h(x0, x1);
                *(uint32_t*)&Cp[rB * ldc + cn] = pack2h(y0, y1);
            } else if (FLAGS & 8) {
                int gc = blockIdx.z * IGD + gn;
                const uint16_t* gbA = g16 + rA * (NHD * TGD) + blockIdx.z * TGD;
                const uint16_t* gbB = g16 + rB * (NHD * TGD) + blockIdx.z * TGD;
                float2 lgA = unp2(*(const uint32_t*)&gbA[gn]);
                float2 igA = unp2(*(const uint32_t*)&gbA[IGD + gn]);
                float2 rgA = unp2(*(const uint32_t*)&gbA[2 * IGD + gn]);
                float2 lgB = unp2(*(const uint32_t*)&gbB[gn]);
                float2 igB = unp2(*(const uint32_t*)&gbB[IGD + gn]);
                float2 rgB = unp2(*(const uint32_t*)&gbB[2 * IGD + gn]);
                float2 liA = unp2(*(const uint32_t*)&l16[rA * ISZ + gc]);
                float2 riA = unp2(*(const uint32_t*)&r16[rA * ISZ + gc]);
                float2 liB = unp2(*(const uint32_t*)&l16[rB * ISZ + gc]);
                float2 riB = unp2(*(const uint32_t*)&r16[rB * ISZ + gc]);
                float o0 = liA.x * lgA.x + igA.x * x0 + riA.x * rgA.x;
                float o1 = liA.y * lgA.y + igA.y * x1 + riA.y * rgA.y;
                float o2 = liB.x * lgB.x + igB.x * y0 + riB.x * rgB.x;
                float o3 = liB.y * lgB.y + igB.y * y1 + riB.y * rgB.y;
                *(uint32_t*)&Cp[rA * ISZ + gc] = pack2h(o0, o1);
                *(uint32_t*)&Cp[rB * ISZ + gc] = pack2h(o2, o3);
            } else if (FLAGS & 16) {
                *(uint32_t*)&Cp[rA * ldc + gn] = pack2h(x0, x1);
                *(uint32_t*)&Cp[rB * ldc + gn] = pack2h(y0, y1);
            } else {
                *(float2*)(C + rA * ldc + gn) = make_float2(x0, x1);
                *(float2*)(C + rB * ldc + gn) = make_float2(y0, y1);
            }
        }
    }
}

// ---------------- conversion kernels ----------------
__global__ void __launch_bounds__(256) icvt_k(const float* __restrict__ src,
                                              uint16_t* __restrict__ p) {
    size_t i = (size_t)blockIdx.x * 256 + threadIdx.x;
    float4 v = ((const float4*)src)[i];
    ((uint2*)p)[i] = pack4h(v);
}

// W [K][N] fp32 -> single fp16 plane [N][K]
__global__ void __launch_bounds__(256) wsplit_k(const float* __restrict__ W,
                                                uint16_t* __restrict__ Tp,
                                                int K, int N) {
    __shared__ float tile[32][33];
    const int n0 = blockIdx.x * 32, k0 = blockIdx.y * 32;
    const float* Wp = W + (size_t)blockIdx.z * K * N;
    uint16_t* Hp = Tp + (size_t)blockIdx.z * K * N;
    int tx = threadIdx.x & 31, ty = threadIdx.x >> 5;
#pragma unroll
    for (int i = 0; i < 4; i++)
        tile[ty + 8 * i][tx] = Wp[(size_t)(k0 + ty + 8 * i) * N + n0 + tx];
    __syncthreads();
#pragma unroll
    for (int i = 0; i < 4; i++) {
        __half h = __float2half_rn(tile[tx][ty + 8 * i]);
        Hp[(size_t)(n0 + ty + 8 * i) * K + k0 + tx] = *(uint16_t*)&h;
    }
}

// ---------------- block reduce ----------------
__device__ __forceinline__ void block_reduce2(float& a, float& b) {
    __shared__ float sh[64];
    int lane = threadIdx.x & 31, wid = threadIdx.x >> 5;
#pragma unroll
    for (int o = 16; o > 0; o >>= 1) {
        a += __shfl_xor_sync(0xffffffffu, a, o);
        b += __shfl_xor_sync(0xffffffffu, b, o);
    }
    if (lane == 0) { sh[wid] = a; sh[32 + wid] = b; }
    __syncthreads();
    if (threadIdx.x < 32) {
        a = (lane < 8) ? sh[lane] : 0.f;
        b = (lane < 8) ? sh[32 + lane] : 0.f;
#pragma unroll
        for (int o = 4; o > 0; o >>= 1) {
            a += __shfl_xor_sync(0xffffffffu, a, o);
            b += __shfl_xor_sync(0xffffffffu, b, o);
        }
        if (lane == 0) { sh[0] = a; sh[32] = b; }
    }
    __syncthreads();
    a = sh[0]; b = sh[32];
}

// ---------------- segmented cumsum (fp16 in, fp32 out), 2 cols/thread ----------------
// 65536 threads: (b*NSEG+seg)*2048 + c2 ; columns c = 2*c2, 2*c2+1
__global__ void __launch_bounds__(256) cumsumA_k() {
    int idx = blockIdx.x * 256 + threadIdx.x;
    int c2 = idx & 2047;
    int t = idx >> 11;
    int b = t >> 3, seg = t & 7;
    const uint32_t* p = (const uint32_t*)(csum16 + ((size_t)b << 24) + (size_t)(seg * SEGL) * CH) + c2;
    float sx = 0.f, sy = 0.f;
#pragma unroll 16
    for (int i = 0; i < SEGL; i++) {
        float2 f = unp2(p[(size_t)i * (CH / 2)]);
        sx += f.x; sy += f.y;
    }
    ((float2*)g_part)[idx] = make_float2(sx, sy);
}

__global__ void __launch_bounds__(256) cumsumC_k() {
    int idx = blockIdx.x * 256 + threadIdx.x;
    int c2 = idx & 2047;
    int t = idx >> 11;
    int b = t >> 3, seg = t & 7;
    const uint32_t* p = (const uint32_t*)(csum16 + ((size_t)b << 24) + (size_t)(seg * SEGL) * CH) + c2;
    float2* q = (float2*)(g_csum + ((size_t)b << 24) + (size_t)(seg * SEGL) * CH) + c2;
    float ax = 0.f, ay = 0.f;
    if (c2 < 1024) {    // forward half (c < 2048)
#pragma unroll
        for (int s2 = 0; s2 < NSEG; s2++)
            if (s2 < seg) {
                float2 f = ((const float2*)g_part)[((b * NSEG + s2) << 11) + c2];
                ax += f.x; ay += f.y;
            }
#pragma unroll 16
        for (int i = 0; i < SEGL; i++) {
            float2 f = unp2(p[(size_t)i * (CH / 2)]);
            ax += f.x; ay += f.y;
            q[(size_t)i * (CH / 2)] = make_float2(ax, ay);
        }
    } else {            // reverse half
#pragma unroll
        for (int s2 = 0; s2 < NSEG; s2++)
            if (s2 > seg) {
                float2 f = ((const float2*)g_part)[((b * NSEG + s2) << 11) + c2];
                ax += f.x; ay += f.y;
            }
#pragma unroll 16
        for (int i = SEGL - 1; i >= 0; i--) {
            float2 f = unp2(p[(size_t)i * (CH / 2)]);
            ax += f.x; ay += f.y;
            q[(size_t)i * (CH / 2)] = make_float2(ax, ay);
        }
    }
}

// ---------------- LN lc/rc -> cell plane + relu'd lci/rci (fp16) ----------------
__global__ void __launch_bounds__(256) ln_lcrc_k(
    const float* __restrict__ gl, const float* __restrict__ bl,
    const float* __restrict__ gr, const float* __restrict__ br_)
{
    const int row = blockIdx.x, side = blockIdx.y;
    const float4* x4 = (const float4*)(g_csum + (size_t)row * CH + side * 2048);
    float4 v[2];
    float s = 0.f, ss = 0.f;
#pragma unroll
    for (int k = 0; k < 2; k++) {
        v[k] = x4[threadIdx.x + k * 256];
        s  += v[k].x + v[k].y + v[k].z + v[k].w;
        ss += v[k].x * v[k].x + v[k].y * v[k].y + v[k].z * v[k].z + v[k].w * v[k].w;
    }
    block_reduce2(s, ss);
    float m  = s * (1.f / 2048.f);
    float rs = rsqrtf(ss * (1.f / 2048.f) - m * m + 1e-6f);

    const float4* g4 = (const float4*)(side ? gr  : gl);
    const float4* b4 = (const float4*)(side ? br_ : bl);
    uint16_t* ibuf = side ? rci16 : lci16;
#pragma unroll
    for (int k = 0; k < 2; k++) {
        int c4 = threadIdx.x + k * 256;
        int c  = c4 * 4;
        float4 gv = g4[c4], bv = b4[c4], xv = v[k];
        float4 o;
        o.x = (xv.x - m) * rs * gv.x + bv.x;
        o.y = (xv.y - m) * rs * gv.y + bv.y;
        o.z = (xv.z - m) * rs * gv.z + bv.z;
        o.w = (xv.w - m) * rs * gv.w + bv.w;
        if (c < 1024) {
            int h = c >> 7, ig = c & 127;
            size_t o16 = (size_t)row * (NHD * TGD) + h * TGD + side * 256 + ig;
            *(uint2*)&cell_p[o16] = pack4h(o);
        } else {
            o.x = fmaxf(o.x, 0.f); o.y = fmaxf(o.y, 0.f);
            o.z = fmaxf(o.z, 0.f); o.w = fmaxf(o.w, 0.f);
            *(uint2*)&ibuf[(size_t)row * ISZ + (c - 1024)] = pack4h(o);
        }
    }
}

// ---------------- LN gates + sigmoid (fp16 in place) ----------------
__global__ void __launch_bounds__(256) ln_g_k(const float* __restrict__ gg,
                                              const float* __restrict__ bg) {
    const int row = blockIdx.x;
    uint2* x2 = (uint2*)(gate16 + (size_t)row * (NHD * TGD));
    float4 v[3];
    float s = 0.f, ss = 0.f;
#pragma unroll
    for (int k = 0; k < 3; k++) {
        uint2 u = x2[threadIdx.x + k * 256];
        float2 a = unp2(u.x), b = unp2(u.y);
        v[k] = make_float4(a.x, a.y, b.x, b.y);
        s  += v[k].x + v[k].y + v[k].z + v[k].w;
        ss += v[k].x * v[k].x + v[k].y * v[k].y + v[k].z * v[k].z + v[k].w * v[k].w;
    }
    block_reduce2(s, ss);
    float m  = s * (1.f / 3072.f);
    float rs = rsqrtf(ss * (1.f / 3072.f) - m * m + 1e-6f);
    const float4* g4 = (const float4*)gg;
    const float4* b4 = (const float4*)bg;
#pragma unroll
    for (int k = 0; k < 3; k++) {
        int c4 = threadIdx.x + k * 256;
        float4 gv = g4[c4], bv = b4[c4], xv = v[k];
        float4 o;
        o.x = 1.f / (1.f + __expf(-((xv.x - m) * rs * gv.x + bv.x)));
        o.y = 1.f / (1.f + __expf(-((xv.y - m) * rs * gv.y + bv.y)));
        o.z = 1.f / (1.f + __expf(-((xv.z - m) * rs * gv.z + bv.z)));
        o.w = 1.f / (1.f + __expf(-((xv.w - m) * rs * gv.w + bv.w)));
        uint2 w;
        w.x = pack2h(o.x, o.y);
        w.y = pack2h(o.z, o.w);
        x2[c4] = w;
    }
}

// ---------------- LN ffn hidden (fp16 in) + relu -> hp plane ----------------
__global__ void __launch_bounds__(256) ln_f_k(const float* __restrict__ gf,
                                              const float* __restrict__ bf) {
    const int row = blockIdx.x;
    const uint2* x2 = (const uint2*)(hpre_p + (size_t)row * (NHD * FGD));
    float4 v[4];
    float s = 0.f, ss = 0.f;
#pragma unroll
    for (int k = 0; k < 4; k++) {
        uint2 u = x2[threadIdx.x + k * 256];
        float2 a = unp2(u.x), b = unp2(u.y);
        v[k] = make_float4(a.x, a.y, b.x, b.y);
        s  += v[k].x + v[k].y + v[k].z + v[k].w;
        ss += v[k].x * v[k].x + v[k].y * v[k].y + v[k].z * v[k].z + v[k].w * v[k].w;
    }
    block_reduce2(s, ss);
    float m  = s * (1.f / 4096.f);
    float rs = rsqrtf(ss * (1.f / 4096.f) - m * m + 1e-6f);
    const float4* g4 = (const float4*)gf;
    const float4* b4 = (const float4*)bf;
#pragma unroll
    for (int k = 0; k < 4; k++) {
        int c4 = threadIdx.x + k * 256;
        float4 gv = g4[c4], bv = b4[c4], xv = v[k];
        float4 o;
        o.x = fmaxf((xv.x - m) * rs * gv.x + bv.x, 0.f);
        o.y = fmaxf((xv.y - m) * rs * gv.y + bv.y, 0.f);
        o.z = fmaxf((xv.z - m) * rs * gv.z + bv.z, 0.f);
        o.w = fmaxf((xv.w - m) * rs * gv.w + bv.w, 0.f);
        *(uint2*)&hp_p[(size_t)row * (NHD * FGD) + c4 * 4] = pack4h(o);
    }
}

// ---------------- host ----------------
extern "C" void kernel_launch(void* const* d_in, const int* in_sizes, int n_in,
                              void* d_out, int out_size) {
    const float* inputs = (const float*)d_in[0];
    const unsigned char* mask = (const unsigned char*)d_in[1];
    const float* W_csum = (const float*)d_in[2];
    const float* b_csum = (const float*)d_in[3];
    const float* W_x    = (const float*)d_in[4];
    const float* b_x    = (const float*)d_in[5];
    const float* gl     = (const float*)d_in[6];
    const float* bel    = (const float*)d_in[7];
    const float* gr     = (const float*)d_in[8];
    const float* ber    = (const float*)d_in[9];
    const float* ggain  = (const float*)d_in[10];
    const float* beg    = (const float*)d_in[11];
    const float* gf     = (const float*)d_in[12];
    const float* bef    = (const float*)d_in[13];
    const float* W_g    = (const float*)d_in[14];
    const float* b_g    = (const float*)d_in[15];
    const float* W_f1   = (const float*)d_in[16];
    const float* b_f1   = (const float*)d_in[17];
    const float* W_f2   = (const float*)d_in[18];
    const float* b_f2   = (const float*)d_in[19];
    const float* W_o    = (const float*)d_in[20];
    const float* b_o    = (const float*)d_in[21];
    float* out = (float*)d_out;

    uint16_t *pcs16, *pg16, *pl16, *pr16;
    cudaGetSymbolAddress((void**)&pcs16, csum16);
    cudaGetSymbolAddress((void**)&pg16,  gate16);
    cudaGetSymbolAddress((void**)&pl16,  lci16);
    cudaGetSymbolAddress((void**)&pr16,  rci16);
    uint16_t *pis, *pcell, *phpre, *php, *ppre;
    uint16_t *pwcs, *pwx, *pwg, *pwf1, *pwf2, *pwo;
    cudaGetSymbolAddress((void**)&pis,   is_p);
    cudaGetSymbolAddress((void**)&pcell, cell_p);
    cudaGetSymbolAddress((void**)&phpre, hpre_p);
    cudaGetSymbolAddress((void**)&php,   hp_p);
    cudaGetSymbolAddress((void**)&ppre,  pre_p);
    cudaGetSymbolAddress((void**)&pwcs, wcs_p);
    cudaGetSymbolAddress((void**)&pwx,  wx_p);
    cudaGetSymbolAddress((void**)&pwg,  wg_p);
    cudaGetSymbolAddress((void**)&pwf1, wf1_p);
    cudaGetSymbolAddress((void**)&pwf2, wf2_p);
    cudaGetSymbolAddress((void**)&pwo,  wo_p);

    cudaFuncSetAttribute(hgemm_k<2>,  cudaFuncAttributeMaxDynamicSharedMemorySize, SMT);
    cudaFuncSetAttribute(hgemm_k<4>,  cudaFuncAttributeMaxDynamicSharedMemorySize, SMT);
    cudaFuncSetAttribute(hgemm_k<8>,  cudaFuncAttributeMaxDynamicSharedMemorySize, SMT);
    cudaFuncSetAttribute(hgemm_k<16>, cudaFuncAttributeMaxDynamicSharedMemorySize, SMT);
    cudaFuncSetAttribute(hgemm_k<17>, cudaFuncAttributeMaxDynamicSharedMemorySize, SMT);

    dim3 blk(256);

    // ---- conversions ----
    icvt_k<<<ROWS * ISZ / 1024, blk>>>(inputs, pis);
    wsplit_k<<<dim3(CH / 32, ISZ / 32, 1), blk>>>(W_csum, pwcs, ISZ, CH);
    wsplit_k<<<dim3(ISZ / 32, ISZ / 32, 1), blk>>>(W_x, pwx, ISZ, ISZ);
    wsplit_k<<<dim3(TGD / 32, TGD / 32, NHD), blk>>>(W_g, pwg, TGD, TGD);
    wsplit_k<<<dim3(FGD / 32, TGD / 32, NHD), blk>>>(W_f1, pwf1, TGD, FGD);
    wsplit_k<<<dim3(IGD / 32, FGD / 32, NHD), blk>>>(W_f2, pwf2, FGD, IGD);
    wsplit_k<<<dim3(ISZ / 32, ISZ / 32, 1), blk>>>(W_o, pwo, ISZ, ISZ);

    // 1) csum GEMM (masked, fp16 out)
    hgemm_k<17><<<dim3(CH / 128, ROWS / 128, 1), blk, SMT>>>(
        pis, ISZ, 0, pwcs, 0, b_csum, 0,
        nullptr, CH, 0, pcs16, CH, ISZ, mask, nullptr, nullptr, nullptr, nullptr);
    // 2) out_x GEMM -> cell plane (remap)
    hgemm_k<4><<<dim3(ISZ / 128, ROWS / 128, 1), blk, SMT>>>(
        pis, ISZ, 0, pwx, 0, b_x, 0,
        nullptr, NHD * TGD, 0, pcell, ISZ, ISZ, nullptr, nullptr, nullptr, nullptr, nullptr);
    // 3) segmented cumsum (fp16 in -> fp32 out), 2 cols/thread
    cumsumA_k<<<256, 256>>>();
    cumsumC_k<<<256, 256>>>();
    // 4) LN lc/rc
    ln_lcrc_k<<<dim3(ROWS, 2), 256>>>(gl, bel, gr, ber);
    // 5) gates GEMM (fp16 out)
    hgemm_k<16><<<dim3(TGD / 128, ROWS / 128, NHD), blk, SMT>>>(
        pcell, NHD * TGD, TGD, pwg, (long)TGD * TGD, b_g, TGD,
        nullptr, NHD * TGD, TGD, pg16, TGD, TGD, nullptr, nullptr, nullptr, nullptr, nullptr);
    // 6) LN gates + sigmoid (fp16 in place)
    ln_g_k<<<ROWS, 256>>>(ggain, beg);
    // 7) ffn1 GEMM -> fp16 pre-LN hidden
    hgemm_k<16><<<dim3(FGD / 128, ROWS / 128, NHD), blk, SMT>>>(
        pcell, NHD * TGD, TGD, pwf1, (long)FGD * TGD, b_f1, FGD,
        nullptr, NHD * FGD, FGD, phpre, FGD, TGD, nullptr, nullptr, nullptr, nullptr, nullptr);
    // 8) LN ffn + relu -> hp plane
    ln_f_k<<<ROWS, 256>>>(gf, bef);
    // 9) ffn2 GEMM + fused combine -> pre plane
    hgemm_k<8><<<dim3(IGD / 128, ROWS / 128, NHD), blk, SMT>>>(
        php, NHD * FGD, FGD, pwf2, (long)IGD * FGD, b_f2, IGD,
        nullptr, ISZ, IGD, ppre, IGD, FGD, nullptr, nullptr, pg16, pl16, pr16);
    // 10) final GEMM + residual
    hgemm_k<2><<<dim3(ISZ / 128, ROWS / 128, 1), blk, SMT>>>(
        ppre, ISZ, 0, pwo, 0, b_o, 0,
        out, ISZ, 0, nullptr, ISZ, ISZ, nullptr, inputs, nullptr, nullptr, nullptr);
}

// round 11
// speedup vs baseline: 1.1097x; 1.1075x over previous
#include <cuda_runtime.h>
#include <cuda_fp16.h>
#include <cstdint>

#define ROWS 16384      // B*S
#define CH   4096
#define NHD  8
#define IGD  128
#define TGD  384
#define FGD  512
#define ISZ  1024
#define NSEG 8
#define SEGL 512        // 4096 / NSEG

// ---------------- scratch ----------------
__device__ float g_csum[(size_t)ROWS * CH];        // GEMM out + in-place scan (fp32)
__device__ float g_part[(size_t)4 * NSEG * CH];    // segment sums

__device__ __align__(16) uint16_t gate16[(size_t)ROWS * NHD * TGD]; // gates fp16
__device__ __align__(16) uint16_t lci16 [(size_t)ROWS * ISZ];
__device__ __align__(16) uint16_t rci16 [(size_t)ROWS * ISZ];

// ---------------- activation planes: single fp16 ----------------
__device__ __align__(16) uint16_t is_p  [(size_t)ROWS * ISZ];
__device__ __align__(16) uint16_t cell_p[(size_t)ROWS * NHD * TGD];
__device__ __align__(16) uint16_t hpre_p[(size_t)ROWS * NHD * FGD];
__device__ __align__(16) uint16_t hp_p  [(size_t)ROWS * NHD * FGD];
__device__ __align__(16) uint16_t pre_p [(size_t)ROWS * ISZ];
// ---------------- weight planes: single fp16, transposed [N][K] ----------------
__device__ __align__(16) uint16_t wcs_p[(size_t)CH * ISZ];
__device__ __align__(16) uint16_t wx_p [(size_t)ISZ * ISZ];
__device__ __align__(16) uint16_t wg_p [(size_t)NHD * TGD * TGD];
__device__ __align__(16) uint16_t wf1_p[(size_t)NHD * FGD * TGD];
__device__ __align__(16) uint16_t wf2_p[(size_t)NHD * IGD * FGD];
__device__ __align__(16) uint16_t wo_p [(size_t)ISZ * ISZ];

// ---------------- helpers ----------------
__device__ __forceinline__ uint32_t smem_u32(const void* p) {
    uint32_t a;
    asm("{ .reg .u64 t; cvta.to.shared.u64 t, %1; cvt.u32.u64 %0, t; }" : "=r"(a) : "l"(p));
    return a;
}
#define CP16(dst, src) asm volatile("cp.async.cg.shared.global [%0], [%1], 16;" :: "r"(dst), "l"(src))
#define CP_COMMIT()    asm volatile("cp.async.commit_group;" ::: "memory")

__device__ __forceinline__ void ldm4(uint32_t& r0, uint32_t& r1, uint32_t& r2, uint32_t& r3, uint32_t a) {
    asm volatile("ldmatrix.sync.aligned.m8n8.x4.shared.b16 {%0,%1,%2,%3}, [%4];"
                 : "=r"(r0), "=r"(r1), "=r"(r2), "=r"(r3) : "r"(a));
}
__device__ __forceinline__ void mma16816(float* d, const uint32_t* a, const uint32_t* b) {
    asm volatile("mma.sync.aligned.m16n8k16.row.col.f32.f16.f16.f32 "
                 "{%0,%1,%2,%3},{%4,%5,%6,%7},{%8,%9},{%0,%1,%2,%3};"
                 : "+f"(d[0]), "+f"(d[1]), "+f"(d[2]), "+f"(d[3])
                 : "r"(a[0]), "r"(a[1]), "r"(a[2]), "r"(a[3]), "r"(b[0]), "r"(b[1]));
}
__device__ __forceinline__ uint32_t pack2h(float x, float y) {
    __half2 v = __floats2half2_rn(x, y);
    return *(uint32_t*)&v;
}
__device__ __forceinline__ uint2 pack4h(float4 v) {
    uint2 r;
    r.x = pack2h(v.x, v.y);
    r.y = pack2h(v.z, v.w);
    return r;
}
__device__ __forceinline__ float2 unp2(uint32_t u) { return __half22float2(*(__half2*)&u); }

// ---------------- fp16 tensor-core GEMM, double-buffered ----------------
// FLAGS: 1 mask, 2 residual(fp32 out), 4 fp16-out remap (out_x), 8 fused-combine (ffn2), 16 fp16-out plain
#define P_A  0
#define P_B  8192
#define STG  16384
#define SMT  32768

template <int FLAGS>
__global__ void __launch_bounds__(256, 2) hgemm_k(
    const uint16_t* __restrict__ Ap, int lda, int aoff,
    const uint16_t* __restrict__ Bp, long boff,
    const float* __restrict__ bias, int biasoff,
    float* __restrict__ C, int ldc, int coff,
    uint16_t* __restrict__ Cp,
    int N, int K,
    const unsigned char* __restrict__ mask,
    const float* __restrict__ resid,
    const uint16_t* __restrict__ g16,   // gates (FLAG8)
    const uint16_t* __restrict__ l16, const uint16_t* __restrict__ r16)
{
    extern __shared__ char smem[];
    const uint32_t sb = smem_u32(smem);
    const int tid = threadIdx.x, wid = tid >> 5, lane = tid & 31;

    Ap += (long)blockIdx.z * aoff;
    Bp += (long)blockIdx.z * boff;
    bias += (long)blockIdx.z * biasoff;
    C  += (long)blockIdx.z * coff;
    Cp += (FLAGS & 16) ? (long)blockIdx.z * coff : 0;

    const int m0 = blockIdx.y * 128;
    const int n0 = blockIdx.x * 128;
    const int warpM = (wid & 1) * 64;
    const int warpN = (wid >> 1) * 32;

    const int rowA = warpM + (lane & 15);
    const int hiA  = (lane >> 4) & 1;
    const int swA  = (rowA >> 1) & 3;
    const uint32_t aRow = sb + P_A + (uint32_t)rowA * 64;

    const int rowB = warpN + (lane & 7) + ((lane & 16) >> 1);
    const int hiB  = (lane >> 3) & 1;
    const int swB  = (rowB >> 1) & 3;
    const uint32_t bRow = sb + P_B + (uint32_t)rowB * 64;

    const int su0 = tid, su1 = tid + 256;
    const int sr0 = su0 >> 2, sc0 = su0 & 3;
    const int sr1 = su1 >> 2, sc1 = su1 & 3;
    const uint32_t sd0 = (uint32_t)sr0 * 64 + ((uint32_t)(sc0 ^ ((sr0 >> 1) & 3)) << 4);
    const uint32_t sd1 = (uint32_t)sr1 * 64 + ((uint32_t)(sc1 ^ ((sr1 >> 1) & 3)) << 4);

    float acc[4][4][4];
#pragma unroll
    for (int i = 0; i < 4; i++)
#pragma unroll
        for (int j = 0; j < 4; j++)
#pragma unroll
            for (int q = 0; q < 4; q++) acc[i][j][q] = 0.f;

    const int nch = K >> 5;

#define STAGE(c, bs) do { \
        const int _k0 = (c) << 5; \
        const uint32_t _b = sb + (bs) * STG; \
        size_t _sa = (size_t)(m0 + sr0) * lda + _k0 + sc0 * 8; \
        CP16(_b + P_A + sd0, Ap + _sa); \
        size_t _sb2 = (size_t)(n0 + sr0) * K + _k0 + sc0 * 8; \
        CP16(_b + P_B + sd0, Bp + _sb2); \
        _sa = (size_t)(m0 + sr1) * lda + _k0 + sc1 * 8; \
        CP16(_b + P_A + sd1, Ap + _sa); \
        _sb2 = (size_t)(n0 + sr1) * K + _k0 + sc1 * 8; \
        CP16(_b + P_B + sd1, Bp + _sb2); \
        CP_COMMIT(); \
    } while (0)

    STAGE(0, 0);
    for (int c = 0; c < nch; c++) {
        const int bs = c & 1;
        if (c + 1 < nch) {
            STAGE(c + 1, bs ^ 1);
            asm volatile("cp.async.wait_group 1;" ::: "memory");
        } else {
            asm volatile("cp.async.wait_group 0;" ::: "memory");
        }
        __syncthreads();

        const uint32_t bb = (uint32_t)bs * STG;
#pragma unroll
        for (int ks = 0; ks < 2; ks++) {
            const uint32_t ca = ((uint32_t)((2 * ks + hiA) ^ swA)) << 4;
            const uint32_t cb = ((uint32_t)((2 * ks + hiB) ^ swB)) << 4;
            uint32_t bf[4][2];
            ldm4(bf[0][0], bf[0][1], bf[1][0], bf[1][1], bRow + bb + cb);
            ldm4(bf[2][0], bf[2][1], bf[3][0], bf[3][1], bRow + bb + 1024 + cb);
#pragma unroll
            for (int mf = 0; mf < 4; mf++) {
                uint32_t af[4];
                ldm4(af[0], af[1], af[2], af[3], aRow + bb + mf * 1024 + ca);
#pragma unroll
                for (int nf = 0; nf < 4; nf++)
                    mma16816(acc[mf][nf], af, bf[nf]);
            }
        }
        __syncthreads();
    }
#undef STAGE

    // ---------------- epilogue ----------------
#pragma unroll
    for (int mf = 0; mf < 4; mf++) {
        long rA = m0 + warpM + mf * 16 + (lane >> 2);
        long rB = rA + 8;
        float zfA = 1.f, zfB = 1.f;
        if (FLAGS & 1) { zfA = mask[rA] ? 0.f : 1.f; zfB = mask[rB] ? 0.f : 1.f; }
#pragma unroll
        for (int nf = 0; nf < 4; nf++) {
            int gn = n0 + warpN + nf * 8 + (lane & 3) * 2;
            float b0 = bias[gn], b1 = bias[gn + 1];
            float x0 = acc[mf][nf][0] + b0, x1 = acc[mf][nf][1] + b1;
            float y0 = acc[mf][nf][2] + b0, y1 = acc[mf][nf][3] + b1;
            if (FLAGS & 1) { x0 *= zfA; x1 *= zfA; y0 *= zfB; y1 *= zfB; }
            if (FLAGS & 2) {
                x0 += resid[rA * N + gn]; x1 += resid[rA * N + gn + 1];
                y0 += resid[rB * N + gn]; y1 += resid[rB * N + gn + 1];
            }
            if (FLAGS & 4) {
                int cn = (gn >> 7) * TGD + IGD + (gn & 127);
                *(uint32_t*)&Cp[rA * ldc + cn] = pack2h(x0, x1);
                *(uint32_t*)&Cp[rB * ldc + cn] = pack2h(y0, y1);
            } else if (FLAGS & 8) {
                int gc = blockIdx.z * IGD + gn;
                const uint16_t* gbA = g16 + rA * (NHD * TGD) + blockIdx.z * TGD;
                const uint16_t* gbB = g16 + rB * (NHD * TGD) + blockIdx.z * TGD;
                float2 lgA = unp2(*(const uint32_t*)&gbA[gn]);
                float2 igA = unp2(*(const uint32_t*)&gbA[IGD + gn]);
                float2 rgA = unp2(*(const uint32_t*)&gbA[2 * IGD + gn]);
                float2 lgB = unp2(*(const uint32_t*)&gbB[gn]);
                float2 igB = unp2(*(const uint32_t*)&gbB[IGD + gn]);
                float2 rgB = unp2(*(const uint32_t*)&gbB[2 * IGD + gn]);
                float2 liA = unp2(*(const uint32_t*)&l16[rA * ISZ + gc]);
                float2 riA = unp2(*(const uint32_t*)&r16[rA * ISZ + gc]);
                float2 liB = unp2(*(const uint32_t*)&l16[rB * ISZ + gc]);
                float2 riB = unp2(*(const uint32_t*)&r16[rB * ISZ + gc]);
                float o0 = liA.x * lgA.x + igA.x * x0 + riA.x * rgA.x;
                float o1 = liA.y * lgA.y + igA.y * x1 + riA.y * rgA.y;
                float o2 = liB.x * lgB.x + igB.x * y0 + riB.x * rgB.x;
                float o3 = liB.y * lgB.y + igB.y * y1 + riB.y * rgB.y;
                *(uint32_t*)&Cp[rA * ISZ + gc] = pack2h(o0, o1);
                *(uint32_t*)&Cp[rB * ISZ + gc] = pack2h(o2, o3);
            } else if (FLAGS & 16) {
                *(uint32_t*)&Cp[rA * ldc + gn] = pack2h(x0, x1);
                *(uint32_t*)&Cp[rB * ldc + gn] = pack2h(y0, y1);
            } else {
                *(float2*)(C + rA * ldc + gn) = make_float2(x0, x1);
                *(float2*)(C + rB * ldc + gn) = make_float2(y0, y1);
            }
        }
    }
}

// ---------------- conversion kernels ----------------
__global__ void __launch_bounds__(256) icvt_k(const float* __restrict__ src,
                                              uint16_t* __restrict__ p) {
    size_t i = (size_t)blockIdx.x * 256 + threadIdx.x;
    float4 v = ((const float4*)src)[i];
    ((uint2*)p)[i] = pack4h(v);
}

// W [K][N] fp32 -> single fp16 plane [N][K]
__global__ void __launch_bounds__(256) wsplit_k(const float* __restrict__ W,
                                                uint16_t* __restrict__ Tp,
                                                int K, int N) {
    __shared__ float tile[32][33];
    const int n0 = blockIdx.x * 32, k0 = blockIdx.y * 32;
    const float* Wp = W + (size_t)blockIdx.z * K * N;
    uint16_t* Hp = Tp + (size_t)blockIdx.z * K * N;
    int tx = threadIdx.x & 31, ty = threadIdx.x >> 5;
#pragma unroll
    for (int i = 0; i < 4; i++)
        tile[ty + 8 * i][tx] = Wp[(size_t)(k0 + ty + 8 * i) * N + n0 + tx];
    __syncthreads();
#pragma unroll
    for (int i = 0; i < 4; i++) {
        __half h = __float2half_rn(tile[tx][ty + 8 * i]);
        Hp[(size_t)(n0 + ty + 8 * i) * K + k0 + tx] = *(uint16_t*)&h;
    }
}

// ---------------- block reduce ----------------
__device__ __forceinline__ void block_reduce2(float& a, float& b) {
    __shared__ float sh[64];
    int lane = threadIdx.x & 31, wid = threadIdx.x >> 5;
#pragma unroll
    for (int o = 16; o > 0; o >>= 1) {
        a += __shfl_xor_sync(0xffffffffu, a, o);
        b += __shfl_xor_sync(0xffffffffu, b, o);
    }
    if (lane == 0) { sh[wid] = a; sh[32 + wid] = b; }
    __syncthreads();
    if (threadIdx.x < 32) {
        a = (lane < 8) ? sh[lane] : 0.f;
        b = (lane < 8) ? sh[32 + lane] : 0.f;
#pragma unroll
        for (int o = 4; o > 0; o >>= 1) {
            a += __shfl_xor_sync(0xffffffffu, a, o);
            b += __shfl_xor_sync(0xffffffffu, b, o);
        }
        if (lane == 0) { sh[0] = a; sh[32] = b; }
    }
    __syncthreads();
    a = sh[0]; b = sh[32];
}

// ---------------- segmented cumsum (fp32, in place — R8 version) ----------------
__global__ void __launch_bounds__(256) cumsumA_k() {
    int idx = blockIdx.x * 256 + threadIdx.x;     // (b*NSEG+seg)*4096 + c
    int c = idx & 4095;
    int t = idx >> 12;
    int b = t >> 3, seg = t & 7;
    const float* p = g_csum + ((size_t)b << 24) + (size_t)(seg * SEGL) * CH + c;
    float s = 0.f;
#pragma unroll 8
    for (int i = 0; i < SEGL; i++) s += p[(size_t)i * CH];
    g_part[idx] = s;
}

__global__ void __launch_bounds__(256) cumsumC_k() {
    int idx = blockIdx.x * 256 + threadIdx.x;
    int c = idx & 4095;
    int t = idx >> 12;
    int b = t >> 3, seg = t & 7;
    float* p = g_csum + ((size_t)b << 24) + (size_t)(seg * SEGL) * CH + c;
    float acc = 0.f;
    if (c < 2048) {
#pragma unroll
        for (int s2 = 0; s2 < NSEG; s2++)
            if (s2 < seg) acc += g_part[((b * NSEG + s2) << 12) + c];
#pragma unroll 8
        for (int i = 0; i < SEGL; i++) { acc += p[(size_t)i * CH]; p[(size_t)i * CH] = acc; }
    } else {
#pragma unroll
        for (int s2 = 0; s2 < NSEG; s2++)
            if (s2 > seg) acc += g_part[((b * NSEG + s2) << 12) + c];
#pragma unroll 8
        for (int i = SEGL - 1; i >= 0; i--) { acc += p[(size_t)i * CH]; p[(size_t)i * CH] = acc; }
    }
}

// ---------------- LN lc/rc -> cell plane + relu'd lci/rci (fp16) ----------------
__global__ void __launch_bounds__(256) ln_lcrc_k(
    const float* __restrict__ gl, const float* __restrict__ bl,
    const float* __restrict__ gr, const float* __restrict__ br_)
{
    const int row = blockIdx.x, side = blockIdx.y;
    const float4* x4 = (const float4*)(g_csum + (size_t)row * CH + side * 2048);
    float4 v[2];
    float s = 0.f, ss = 0.f;
#pragma unroll
    for (int k = 0; k < 2; k++) {
        v[k] = x4[threadIdx.x + k * 256];
        s  += v[k].x + v[k].y + v[k].z + v[k].w;
        ss += v[k].x * v[k].x + v[k].y * v[k].y + v[k].z * v[k].z + v[k].w * v[k].w;
    }
    block_reduce2(s, ss);
    float m  = s * (1.f / 2048.f);
    float rs = rsqrtf(ss * (1.f / 2048.f) - m * m + 1e-6f);

    const float4* g4 = (const float4*)(side ? gr  : gl);
    const float4* b4 = (const float4*)(side ? br_ : bl);
    uint16_t* ibuf = side ? rci16 : lci16;
#pragma unroll
    for (int k = 0; k < 2; k++) {
        int c4 = threadIdx.x + k * 256;
        int c  = c4 * 4;
        float4 gv = g4[c4], bv = b4[c4], xv = v[k];
        float4 o;
        o.x = (xv.x - m) * rs * gv.x + bv.x;
        o.y = (xv.y - m) * rs * gv.y + bv.y;
        o.z = (xv.z - m) * rs * gv.z + bv.z;
        o.w = (xv.w - m) * rs * gv.w + bv.w;
        if (c < 1024) {
            int h = c >> 7, ig = c & 127;
            size_t o16 = (size_t)row * (NHD * TGD) + h * TGD + side * 256 + ig;
            *(uint2*)&cell_p[o16] = pack4h(o);
        } else {
            o.x = fmaxf(o.x, 0.f); o.y = fmaxf(o.y, 0.f);
            o.z = fmaxf(o.z, 0.f); o.w = fmaxf(o.w, 0.f);
            *(uint2*)&ibuf[(size_t)row * ISZ + (c - 1024)] = pack4h(o);
        }
    }
}

// ---------------- LN gates + sigmoid (fp16 in place) ----------------
__global__ void __launch_bounds__(256) ln_g_k(const float* __restrict__ gg,
                                              const float* __restrict__ bg) {
    const int row = blockIdx.x;
    uint2* x2 = (uint2*)(gate16 + (size_t)row * (NHD * TGD));
    float4 v[3];
    float s = 0.f, ss = 0.f;
#pragma unroll
    for (int k = 0; k < 3; k++) {
        uint2 u = x2[threadIdx.x + k * 256];
        float2 a = unp2(u.x), b = unp2(u.y);
        v[k] = make_float4(a.x, a.y, b.x, b.y);
        s  += v[k].x + v[k].y + v[k].z + v[k].w;
        ss += v[k].x * v[k].x + v[k].y * v[k].y + v[k].z * v[k].z + v[k].w * v[k].w;
    }
    block_reduce2(s, ss);
    float m  = s * (1.f / 3072.f);
    float rs = rsqrtf(ss * (1.f / 3072.f) - m * m + 1e-6f);
    const float4* g4 = (const float4*)gg;
    const float4* b4 = (const float4*)bg;
#pragma unroll
    for (int k = 0; k < 3; k++) {
        int c4 = threadIdx.x + k * 256;
        float4 gv = g4[c4], bv = b4[c4], xv = v[k];
        float4 o;
        o.x = 1.f / (1.f + __expf(-((xv.x - m) * rs * gv.x + bv.x)));
        o.y = 1.f / (1.f + __expf(-((xv.y - m) * rs * gv.y + bv.y)));
        o.z = 1.f / (1.f + __expf(-((xv.z - m) * rs * gv.z + bv.z)));
        o.w = 1.f / (1.f + __expf(-((xv.w - m) * rs * gv.w + bv.w)));
        uint2 w;
        w.x = pack2h(o.x, o.y);
        w.y = pack2h(o.z, o.w);
        x2[c4] = w;
    }
}

// ---------------- LN ffn hidden (fp16 in) + relu -> hp plane ----------------
__global__ void __launch_bounds__(256) ln_f_k(const float* __restrict__ gf,
                                              const float* __restrict__ bf) {
    const int row = blockIdx.x;
    const uint2* x2 = (const uint2*)(hpre_p + (size_t)row * (NHD * FGD));
    float4 v[4];
    float s = 0.f, ss = 0.f;
#pragma unroll
    for (int k = 0; k < 4; k++) {
        uint2 u = x2[threadIdx.x + k * 256];
        float2 a = unp2(u.x), b = unp2(u.y);
        v[k] = make_float4(a.x, a.y, b.x, b.y);
        s  += v[k].x + v[k].y + v[k].z + v[k].w;
        ss += v[k].x * v[k].x + v[k].y * v[k].y + v[k].z * v[k].z + v[k].w * v[k].w;
    }
    block_reduce2(s, ss);
    float m  = s * (1.f / 4096.f);
    float rs = rsqrtf(ss * (1.f / 4096.f) - m * m + 1e-6f);
    const float4* g4 = (const float4*)gf;
    const float4* b4 = (const float4*)bf;
#pragma unroll
    for (int k = 0; k < 4; k++) {
        int c4 = threadIdx.x + k * 256;
        float4 gv = g4[c4], bv = b4[c4], xv = v[k];
        float4 o;
        o.x = fmaxf((xv.x - m) * rs * gv.x + bv.x, 0.f);
        o.y = fmaxf((xv.y - m) * rs * gv.y + bv.y, 0.f);
        o.z = fmaxf((xv.z - m) * rs * gv.z + bv.z, 0.f);
        o.w = fmaxf((xv.w - m) * rs * gv.w + bv.w, 0.f);
        *(uint2*)&hp_p[(size_t)row * (NHD * FGD) + c4 * 4] = pack4h(o);
    }
}

// ---------------- host ----------------
extern "C" void kernel_launch(void* const* d_in, const int* in_sizes, int n_in,
                              void* d_out, int out_size) {
    const float* inputs = (const float*)d_in[0];
    const unsigned char* mask = (const unsigned char*)d_in[1];
    const float* W_csum = (const float*)d_in[2];
    const float* b_csum = (const float*)d_in[3];
    const float* W_x    = (const float*)d_in[4];
    const float* b_x    = (const float*)d_in[5];
    const float* gl     = (const float*)d_in[6];
    const float* bel    = (const float*)d_in[7];
    const float* gr     = (const float*)d_in[8];
    const float* ber    = (const float*)d_in[9];
    const float* ggain  = (const float*)d_in[10];
    const float* beg    = (const float*)d_in[11];
    const float* gf     = (const float*)d_in[12];
    const float* bef    = (const float*)d_in[13];
    const float* W_g    = (const float*)d_in[14];
    const float* b_g    = (const float*)d_in[15];
    const float* W_f1   = (const float*)d_in[16];
    const float* b_f1   = (const float*)d_in[17];
    const float* W_f2   = (const float*)d_in[18];
    const float* b_f2   = (const float*)d_in[19];
    const float* W_o    = (const float*)d_in[20];
    const float* b_o    = (const float*)d_in[21];
    float* out = (float*)d_out;

    float* p_csum;
    cudaGetSymbolAddress((void**)&p_csum, g_csum);
    uint16_t *pg16, *pl16, *pr16;
    cudaGetSymbolAddress((void**)&pg16,  gate16);
    cudaGetSymbolAddress((void**)&pl16,  lci16);
    cudaGetSymbolAddress((void**)&pr16,  rci16);
    uint16_t *pis, *pcell, *phpre, *php, *ppre;
    uint16_t *pwcs, *pwx, *pwg, *pwf1, *pwf2, *pwo;
    cudaGetSymbolAddress((void**)&pis,   is_p);
    cudaGetSymbolAddress((void**)&pcell, cell_p);
    cudaGetSymbolAddress((void**)&phpre, hpre_p);
    cudaGetSymbolAddress((void**)&php,   hp_p);
    cudaGetSymbolAddress((void**)&ppre,  pre_p);
    cudaGetSymbolAddress((void**)&pwcs, wcs_p);
    cudaGetSymbolAddress((void**)&pwx,  wx_p);
    cudaGetSymbolAddress((void**)&pwg,  wg_p);
    cudaGetSymbolAddress((void**)&pwf1, wf1_p);
    cudaGetSymbolAddress((void**)&pwf2, wf2_p);
    cudaGetSymbolAddress((void**)&pwo,  wo_p);

    cudaFuncSetAttribute(hgemm_k<1>,  cudaFuncAttributeMaxDynamicSharedMemorySize, SMT);
    cudaFuncSetAttribute(hgemm_k<2>,  cudaFuncAttributeMaxDynamicSharedMemorySize, SMT);
    cudaFuncSetAttribute(hgemm_k<4>,  cudaFuncAttributeMaxDynamicSharedMemorySize, SMT);
    cudaFuncSetAttribute(hgemm_k<8>,  cudaFuncAttributeMaxDynamicSharedMemorySize, SMT);
    cudaFuncSetAttribute(hgemm_k<16>, cudaFuncAttributeMaxDynamicSharedMemorySize, SMT);

    dim3 blk(256);

    // ---- conversions ----
    icvt_k<<<ROWS * ISZ / 1024, blk>>>(inputs, pis);
    wsplit_k<<<dim3(CH / 32, ISZ / 32, 1), blk>>>(W_csum, pwcs, ISZ, CH);
    wsplit_k<<<dim3(ISZ / 32, ISZ / 32, 1), blk>>>(W_x, pwx, ISZ, ISZ);
    wsplit_k<<<dim3(TGD / 32, TGD / 32, NHD), blk>>>(W_g, pwg, TGD, TGD);
    wsplit_k<<<dim3(FGD / 32, TGD / 32, NHD), blk>>>(W_f1, pwf1, TGD, FGD);
    wsplit_k<<<dim3(IGD / 32, FGD / 32, NHD), blk>>>(W_f2, pwf2, FGD, IGD);
    wsplit_k<<<dim3(ISZ / 32, ISZ / 32, 1), blk>>>(W_o, pwo, ISZ, ISZ);

    // 1) csum GEMM (masked, fp32 out — R8 path)
    hgemm_k<1><<<dim3(CH / 128, ROWS / 128, 1), blk, SMT>>>(
        pis, ISZ, 0, pwcs, 0, b_csum, 0,
        p_csum, CH, 0, nullptr, CH, ISZ, mask, nullptr, nullptr, nullptr, nullptr);
    // 2) out_x GEMM -> cell plane (remap)
    hgemm_k<4><<<dim3(ISZ / 128, ROWS / 128, 1), blk, SMT>>>(
        pis, ISZ, 0, pwx, 0, b_x, 0,
        nullptr, NHD * TGD, 0, pcell, ISZ, ISZ, nullptr, nullptr, nullptr, nullptr, nullptr);
    // 3) segmented cumsum (fp32 in place — R8 kernels)
    cumsumA_k<<<512, 256>>>();
    cumsumC_k<<<512, 256>>>();
    // 4) LN lc/rc -> cell + fp16 lci/rci
    ln_lcrc_k<<<dim3(ROWS, 2), 256>>>(gl, bel, gr, ber);
    // 5) gates GEMM (fp16 out)
    hgemm_k<16><<<dim3(TGD / 128, ROWS / 128, NHD), blk, SMT>>>(
        pcell, NHD * TGD, TGD, pwg, (long)TGD * TGD, b_g, TGD,
        nullptr, NHD * TGD, TGD, pg16, TGD, TGD, nullptr, nullptr, nullptr, nullptr, nullptr);
    // 6) LN gates + sigmoid (fp16 in place)
    ln_g_k<<<ROWS, 256>>>(ggain, beg);
    // 7) ffn1 GEMM -> fp16 pre-LN hidden
    hgemm_k<16><<<dim3(FGD / 128, ROWS / 128, NHD), blk, SMT>>>(
        pcell, NHD * TGD, TGD, pwf1, (long)FGD * TGD, b_f1, FGD,
        nullptr, NHD * FGD, FGD, phpre, FGD, TGD, nullptr, nullptr, nullptr, nullptr, nullptr);
    // 8) LN ffn + relu -> hp plane
    ln_f_k<<<ROWS, 256>>>(gf, bef);
    // 9) ffn2 GEMM + fused combine -> pre plane
    hgemm_k<8><<<dim3(IGD / 128, ROWS / 128, NHD), blk, SMT>>>(
        php, NHD * FGD, FGD, pwf2, (long)IGD * FGD, b_f2, IGD,
        nullptr, ISZ, IGD, ppre, IGD, FGD, nullptr, nullptr, pg16, pl16, pr16);
    // 10) final GEMM + residual
    hgemm_k<2><<<dim3(ISZ / 128, ROWS / 128, 1), blk, SMT>>>(
        ppre, ISZ, 0, pwo, 0, b_o, 0,
        out, ISZ, 0, nullptr, ISZ, ISZ, nullptr, inputs, nullptr, nullptr, nullptr);
}